// round 8
// baseline (speedup 1.0000x reference)
#include <cuda_runtime.h>
#include <cstdint>

#define BB 8
#define TT 4096
#define DM 512

// projected Q, K, V scratch (allocation-free rule -> device globals)
// K and V are pre-rounded to tf32 (rna) so attention can feed raw bits to HMMA.
__device__ __align__(256) float g_Q[BB * TT * 64];
__device__ __align__(256) float g_K[BB * TT * 64];
__device__ __align__(256) float g_V[BB * TT * 64];

// ---------------------------------------------------------------------------
// helpers
// ---------------------------------------------------------------------------
__device__ __forceinline__ uint32_t smem_to_u32(const void* p) {
    uint32_t a;
    asm("{ .reg .u64 t; cvta.to.shared.u64 t, %1; cvt.u32.u64 %0, t; }" : "=r"(a) : "l"(p));
    return a;
}
__device__ __forceinline__ uint32_t cvt_tf32(float x) {
    uint32_t u; asm("cvt.rna.tf32.f32 %0, %1;" : "=r"(u) : "f"(x)); return u;
}
__device__ __forceinline__ float ex2f(float x) {
    float y; asm("ex2.approx.ftz.f32 %0, %1;" : "=f"(y) : "f"(x)); return y;
}
// D += A(tf32, m16 x k8) * B(tf32, k8 x n8)
__device__ __forceinline__ void mma8(float* d, const uint32_t* a, const uint32_t* b) {
    asm volatile(
        "mma.sync.aligned.m16n8k8.row.col.f32.tf32.tf32.f32 "
        "{%0,%1,%2,%3}, {%4,%5,%6,%7}, {%8,%9}, {%0,%1,%2,%3};"
        : "+f"(d[0]), "+f"(d[1]), "+f"(d[2]), "+f"(d[3])
        : "r"(a[0]), "r"(a[1]), "r"(a[2]), "r"(a[3]), "r"(b[0]), "r"(b[1]));
}
__device__ __forceinline__ void cp16(uint32_t dst, const void* src) {
    asm volatile("cp.async.ca.shared.global [%0], [%1], 16;" :: "r"(dst), "l"(src));
}
__device__ __forceinline__ void cp_commit() { asm volatile("cp.async.commit_group;"); }
template<int N> __device__ __forceinline__ void cp_wait() {
    asm volatile("cp.async.wait_group %0;" :: "n"(N));
}
__device__ __forceinline__ uint32_t fb(float x) { return __float_as_uint(x); }

// ---------------------------------------------------------------------------
// Projection: Y[32768,64] = X[32768,512] @ W[512,64], 2-term split-tf32
// (x_hi@w + x_lo@w, w rounded to tf32 per use). K chunks of 32, double-buffered.
// K/V outputs rounded to tf32 for raw-bit HMMA feeding in attention.
// ---------------------------------------------------------------------------
#define PX_PAD 36
#define PW_PAD 72
#define P_X0 0
#define P_X1 18432
#define P_W0 36864
#define P_W1 46080
#define P_TOT 55296

__global__ void __launch_bounds__(256, 2) proj_kernel(
    const float* __restrict__ Xq, const float* __restrict__ Xk, const float* __restrict__ Xv,
    const float* __restrict__ Wq, const float* __restrict__ Wk, const float* __restrict__ Wv)
{
    extern __shared__ char sm[];
    uint32_t smb = smem_to_u32(sm);

    const float* X; const float* W; float* Y;
    int which = blockIdx.y;
    if (which == 0)      { X = Xq; W = Wq; Y = g_Q; }
    else if (which == 1) { X = Xk; W = Wk; Y = g_K; }
    else                 { X = Xv; W = Wv; Y = g_V; }

    const int tid = threadIdx.x, lane = tid & 31, warp = tid >> 5;
    const int r4 = lane >> 2, k4 = lane & 3;
    const int rowBase = blockIdx.x * 128;

    auto load_chunk = [&](int ch) {
        uint32_t xd = smb + ((ch & 1) ? P_X1 : P_X0);
        uint32_t wd = smb + ((ch & 1) ? P_W1 : P_W0);
        const float* xs = X + (size_t)rowBase * DM + ch * 32;
        #pragma unroll
        for (int i = 0; i < 4; i++) {
            int idx = tid + i * 256;
            int row = idx >> 3, c = idx & 7;
            cp16(xd + row * (PX_PAD * 4) + c * 16, xs + (size_t)row * DM + c * 4);
        }
        const float* ws = W + (size_t)(ch * 32) * 64;
        #pragma unroll
        for (int i = 0; i < 2; i++) {
            int idx = tid + i * 256;
            int row = idx >> 4, c = idx & 15;
            cp16(wd + row * (PW_PAD * 4) + c * 16, ws + row * 64 + c * 4);
        }
        cp_commit();
    };

    float acc[8][4];
    #pragma unroll
    for (int nb = 0; nb < 8; nb++)
        #pragma unroll
        for (int i = 0; i < 4; i++) acc[nb][i] = 0.0f;

    load_chunk(0);
    for (int ch = 0; ch < 16; ch++) {
        if (ch > 0) __syncthreads();
        if (ch < 15) load_chunk(ch + 1);
        if (ch < 15) cp_wait<1>(); else cp_wait<0>();
        __syncthreads();

        const float* Xs = (const float*)(sm + ((ch & 1) ? P_X1 : P_X0));
        const float* Ws = (const float*)(sm + ((ch & 1) ? P_W1 : P_W0));

        #pragma unroll
        for (int ks = 0; ks < 4; ks++) {
            const float* xp = Xs + (warp * 16 + r4) * PX_PAD + ks * 8 + k4;
            float af[4] = { xp[0], xp[8 * PX_PAD], xp[4], xp[8 * PX_PAD + 4] };
            uint32_t ahi[4], alo[4];
            #pragma unroll
            for (int i = 0; i < 4; i++) {
                uint32_t h = __float_as_uint(af[i]) & 0xffffe000u;
                ahi[i] = h;
                alo[i] = cvt_tf32(af[i] - __uint_as_float(h));
            }
            const float* wp = Ws + (ks * 8 + k4) * PW_PAD;
            #pragma unroll
            for (int nb = 0; nb < 8; nb++) {
                uint32_t bb[2] = {
                    cvt_tf32(wp[nb * 8 + r4]),
                    cvt_tf32(wp[4 * PW_PAD + nb * 8 + r4])
                };
                mma8(acc[nb], ahi, bb);
                mma8(acc[nb], alo, bb);
            }
        }
    }

    // K and V: round to tf32 (rna) so the attention kernel can skip cvts.
    if (which != 0) {
        #pragma unroll
        for (int nb = 0; nb < 8; nb++)
            #pragma unroll
            for (int i = 0; i < 4; i++)
                acc[nb][i] = __uint_as_float(cvt_tf32(acc[nb][i]));
    }

    float* yp = Y + (size_t)(rowBase + warp * 16) * 64;
    #pragma unroll
    for (int nb = 0; nb < 8; nb++) {
        int c = nb * 8 + 2 * k4;
        *(float2*)(yp + r4 * 64 + c)       = make_float2(acc[nb][0], acc[nb][1]);
        *(float2*)(yp + (r4 + 8) * 64 + c) = make_float2(acc[nb][2], acc[nb][3]);
    }
}

// ---------------------------------------------------------------------------
// Flash attention, software-pipelined. CTA = (128 q-rows, batch); 8 warps,
// each warp m16 x n64; Bc=64, 64 tiles. 1 CTA/SM, fat registers.
//
// Pipeline per iteration t:
//   wait(tile t+1) -> issue S(t+1) mmas into the spare S buffer
//   softmax(t) scalar work overlaps the S(t+1) tensor drain
//   PV(t) mmas -> barrier -> issue cp.async for tile t+2
// The tensor pipe always has >=64-mma backlog across scalar/barrier windows.
// ---------------------------------------------------------------------------
#define AQ_PAD 68
#define AK_PAD 68
#define AV_PAD 72
#define A_BIAS 0                       // 4096 floats = 16384
#define A_Q    16384                   // 128*68*4 = 34816 -> 51200
#define A_K0   51200                   // 64*68*4 = 17408 -> 68608
#define A_K1   68608                   // -> 86016
#define A_V0   86016                   // 64*72*4 = 18432 -> 104448
#define A_V1   104448                  // -> 122880
#define A_TOT  122880

__global__ void __launch_bounds__(256, 1) attn_kernel(
    const int* __restrict__ pad_mask, float* __restrict__ out)
{
    extern __shared__ char sm[];
    uint32_t smb = smem_to_u32(sm);
    float* biasAll = (float*)(sm + A_BIAS);

    const int tid = threadIdx.x, lane = tid & 31, warp = tid >> 5;
    const int b = blockIdx.y, qBase = blockIdx.x * 128;
    const int r4 = lane >> 2, k4 = lane & 3;

    const float* gK = g_K + (size_t)b * TT * 64;
    const float* gV = g_V + (size_t)b * TT * 64;
    const int*   pm = pad_mask + (size_t)b * TT;

    auto load_tile = [&](int t) {
        int base = t * 64;
        uint32_t kd = smb + ((t & 1) ? A_K1 : A_K0);
        uint32_t vd = smb + ((t & 1) ? A_V1 : A_V0);
        #pragma unroll
        for (int i = 0; i < 4; i++) {
            int idx = tid + i * 256;
            int row = idx >> 4, c = idx & 15;
            cp16(kd + row * (AK_PAD * 4) + c * 16, gK + (size_t)(base + row) * 64 + c * 4);
            // V rows permuted within each 8-group: actual row r -> slot
            // (r&1) ? r/2+4 : r/2, so the S-acc fragment is the PV A-fragment.
            int r7 = row & 7;
            int vrow = (row & ~7) | ((r7 & 1) ? ((r7 >> 1) + 4) : (r7 >> 1));
            cp16(vd + vrow * (AV_PAD * 4) + c * 16, gV + (size_t)(base + row) * 64 + c * 4);
        }
        cp_commit();
    };

    // prologue: stage Q (group), tile 0 (group), tile 1 (group)
    {
        const float* src = g_Q + ((size_t)b * TT + qBase) * 64;
        #pragma unroll
        for (int i = 0; i < 8; i++) {
            int idx = tid + i * 256;
            int row = idx >> 4, c = idx & 15;
            cp16(smb + A_Q + row * (AQ_PAD * 4) + c * 16, src + row * 64 + c * 4);
        }
        cp_commit();
    }
    load_tile(0);
    load_tile(1);

    // mask bias precompute (overlaps the async loads)
    for (int i = tid; i < TT; i += 256)
        biasAll[i] = pm[i] ? -1e30f : 0.0f;

    cp_wait<1>();          // Q + tile0 complete (tile1 may be pending)
    __syncthreads();

    // persistent Q fragments: scale by (1/sqrt(512))*log2(e), tf32-round once
    const float qscale = 0.044194173824159216f * 1.4426950408889634f;
    uint32_t Qr[8][4];
    {
        const float* Qs = (const float*)(sm + A_Q);
        int r0 = warp * 16 + r4;
        #pragma unroll
        for (int ks = 0; ks < 8; ks++) {
            int c0 = ks * 8 + k4;
            Qr[ks][0] = cvt_tf32(Qs[r0 * AQ_PAD + c0] * qscale);
            Qr[ks][1] = cvt_tf32(Qs[(r0 + 8) * AQ_PAD + c0] * qscale);
            Qr[ks][2] = cvt_tf32(Qs[r0 * AQ_PAD + c0 + 4] * qscale);
            Qr[ks][3] = cvt_tf32(Qs[(r0 + 8) * AQ_PAD + c0 + 4] * qscale);
        }
    }

    float o[8][4];
    float sA[8][4], sB[8][4];
    float l0 = 0.0f, l1 = 0.0f;
    #pragma unroll
    for (int nb = 0; nb < 8; nb++)
        #pragma unroll
        for (int i = 0; i < 4; i++) { o[nb][i] = 0.0f; sA[nb][i] = 0.0f; }

    // issue S(0) into sA (K0 ready; same barrier epoch)
    {
        const float* Ks = (const float*)(sm + A_K0);
        #pragma unroll
        for (int ks = 0; ks < 8; ks++) {
            const float* kp = Ks + ks * 8 + k4;
            #pragma unroll
            for (int nb = 0; nb < 8; nb++) {
                const float* kk = kp + (nb * 8 + r4) * AK_PAD;
                uint32_t bb[2] = { fb(kk[0]), fb(kk[4]) };
                mma8(sA[nb], Qr[ks], bb);
            }
        }
    }

    const int NT = TT / 64;

    // pipelined body: consume s_cur (= S(t)), produce s_nxt (= S(t+1))
    auto body = [&](int t, float (&s_cur)[8][4], float (&s_nxt)[8][4]) {
        cp_wait<0>();
        __syncthreads();                       // tile t+1 visible

        // issue S(t+1) -> s_nxt (tensor backlog covers the scalar phase below)
        if (t + 1 < NT) {
            #pragma unroll
            for (int nb = 0; nb < 8; nb++)
                #pragma unroll
                for (int i = 0; i < 4; i++) s_nxt[nb][i] = 0.0f;
            const float* Ks = (const float*)(sm + (((t + 1) & 1) ? A_K1 : A_K0));
            #pragma unroll
            for (int ks = 0; ks < 8; ks++) {
                const float* kp = Ks + ks * 8 + k4;
                #pragma unroll
                for (int nb = 0; nb < 8; nb++) {
                    const float* kk = kp + (nb * 8 + r4) * AK_PAD;
                    uint32_t bb[2] = { fb(kk[0]), fb(kk[4]) };
                    mma8(s_nxt[nb], Qr[ks], bb);
                }
            }
        }

        // softmax(t): p = exp2(s + bias), tf32-rounded; l sums the ROUNDED p
        // so P-rounding bias cancels in the final normalization.
        const float* bias = biasAll + t * 64;
        #pragma unroll
        for (int nb = 0; nb < 8; nb++) {
            int c = nb * 8 + 2 * k4;
            float2 bv = *(const float2*)(bias + c);
            float p0 = __uint_as_float(cvt_tf32(ex2f(s_cur[nb][0] + bv.x)));
            float p1 = __uint_as_float(cvt_tf32(ex2f(s_cur[nb][1] + bv.y)));
            float p2 = __uint_as_float(cvt_tf32(ex2f(s_cur[nb][2] + bv.x)));
            float p3 = __uint_as_float(cvt_tf32(ex2f(s_cur[nb][3] + bv.y)));
            l0 += p0 + p1;
            l1 += p2 + p3;
            s_cur[nb][0] = p0; s_cur[nb][1] = p1;
            s_cur[nb][2] = p2; s_cur[nb][3] = p3;
        }

        // PV(t): S-acc fragment IS the A-fragment (V rows permuted at load).
        const float* Vs = (const float*)(sm + ((t & 1) ? A_V1 : A_V0));
        #pragma unroll
        for (int ks = 0; ks < 8; ks++) {
            uint32_t a[4] = { fb(s_cur[ks][0]), fb(s_cur[ks][2]),
                              fb(s_cur[ks][1]), fb(s_cur[ks][3]) };
            const float* vp = Vs + (ks * 8 + k4) * AV_PAD;
            #pragma unroll
            for (int nb = 0; nb < 8; nb++) {
                uint32_t bb[2] = { fb(vp[nb * 8 + r4]), fb(vp[4 * AV_PAD + nb * 8 + r4]) };
                mma8(o[nb], a, bb);
            }
        }

        __syncthreads();                       // K(t)/V(t) reads complete
        if (t + 2 < NT) load_tile(t + 2);      // overwrite buffer (t&1)
    };

    #pragma unroll 1
    for (int tt = 0; tt < NT; tt += 2) {
        body(tt,     sA, sB);
        body(tt + 1, sB, sA);
    }

    // reduce row-sums across the quad, normalize, store
    l0 += __shfl_xor_sync(0xffffffffu, l0, 1);
    l0 += __shfl_xor_sync(0xffffffffu, l0, 2);
    l1 += __shfl_xor_sync(0xffffffffu, l1, 1);
    l1 += __shfl_xor_sync(0xffffffffu, l1, 2);
    float i0 = 1.0f / l0, i1 = 1.0f / l1;

    float* op = out + ((size_t)b * TT + qBase + warp * 16) * 64;
    #pragma unroll
    for (int nb = 0; nb < 8; nb++) {
        int c = nb * 8 + 2 * k4;
        *(float2*)(op + r4 * 64 + c)       = make_float2(o[nb][0] * i0, o[nb][1] * i0);
        *(float2*)(op + (r4 + 8) * 64 + c) = make_float2(o[nb][2] * i1, o[nb][3] * i1);
    }
}

// ---------------------------------------------------------------------------
// kernel_launch: inputs (metadata order): k, v, q, pad_mask, Wk, Wq, Wv
// ---------------------------------------------------------------------------
extern "C" void kernel_launch(void* const* d_in, const int* in_sizes, int n_in,
                              void* d_out, int out_size)
{
    const float* k        = (const float*)d_in[0];
    const float* v        = (const float*)d_in[1];
    const float* q        = (const float*)d_in[2];
    const int*   pad_mask = (const int*)d_in[3];
    const float* Wk       = (const float*)d_in[4];
    const float* Wq       = (const float*)d_in[5];
    const float* Wv       = (const float*)d_in[6];
    float* out = (float*)d_out;

    cudaFuncSetAttribute(proj_kernel, cudaFuncAttributeMaxDynamicSharedMemorySize, P_TOT);
    dim3 pg(BB * TT / 128, 3);
    proj_kernel<<<pg, 256, P_TOT>>>(q, k, v, Wq, Wk, Wv);

    cudaFuncSetAttribute(attn_kernel, cudaFuncAttributeMaxDynamicSharedMemorySize, A_TOT);
    dim3 ag(TT / 128, BB);
    attn_kernel<<<ag, 256, A_TOT>>>(pad_mask, out);
}

// round 9
// speedup vs baseline: 1.6964x; 1.6964x over previous
#include <cuda_runtime.h>
#include <cuda_fp16.h>
#include <cstdint>

#define BB 8
#define TT 4096
#define DM 512

// projected Q, K, V scratch (fp16). Q pre-scaled by (1/sqrt(512))*log2(e).
// V stored TRANSPOSED: g_Vt[b][d][t].
__device__ __align__(256) __half g_Qh[BB * TT * 64];
__device__ __align__(256) __half g_Kh[BB * TT * 64];
__device__ __align__(256) __half g_Vt[BB * 64 * TT];

// ---------------------------------------------------------------------------
// helpers
// ---------------------------------------------------------------------------
__device__ __forceinline__ uint32_t smem_to_u32(const void* p) {
    uint32_t a;
    asm("{ .reg .u64 t; cvta.to.shared.u64 t, %1; cvt.u32.u64 %0, t; }" : "=r"(a) : "l"(p));
    return a;
}
__device__ __forceinline__ uint32_t cvt_tf32(float x) {
    uint32_t u; asm("cvt.rna.tf32.f32 %0, %1;" : "=r"(u) : "f"(x)); return u;
}
__device__ __forceinline__ float ex2f(float x) {
    float y; asm("ex2.approx.ftz.f32 %0, %1;" : "=f"(y) : "f"(x)); return y;
}
// pack two f32 -> f16x2 (lo = first arg)
__device__ __forceinline__ uint32_t pack_h2(float lo, float hi) {
    uint32_t d; asm("cvt.rn.f16x2.f32 %0, %1, %2;" : "=r"(d) : "f"(hi), "f"(lo)); return d;
}
// tf32: D += A(m16 x k8) * B(k8 x n8)
__device__ __forceinline__ void mma8(float* d, const uint32_t* a, const uint32_t* b) {
    asm volatile(
        "mma.sync.aligned.m16n8k8.row.col.f32.tf32.tf32.f32 "
        "{%0,%1,%2,%3}, {%4,%5,%6,%7}, {%8,%9}, {%0,%1,%2,%3};"
        : "+f"(d[0]), "+f"(d[1]), "+f"(d[2]), "+f"(d[3])
        : "r"(a[0]), "r"(a[1]), "r"(a[2]), "r"(a[3]), "r"(b[0]), "r"(b[1]));
}
// fp16: D += A(m16 x k16) * B(k16 x n8), f32 accumulate
__device__ __forceinline__ void mma16(float* d, const uint32_t* a, const uint32_t* b) {
    asm volatile(
        "mma.sync.aligned.m16n8k16.row.col.f32.f16.f16.f32 "
        "{%0,%1,%2,%3}, {%4,%5,%6,%7}, {%8,%9}, {%0,%1,%2,%3};"
        : "+f"(d[0]), "+f"(d[1]), "+f"(d[2]), "+f"(d[3])
        : "r"(a[0]), "r"(a[1]), "r"(a[2]), "r"(a[3]), "r"(b[0]), "r"(b[1]));
}
__device__ __forceinline__ void cp16(uint32_t dst, const void* src) {
    asm volatile("cp.async.ca.shared.global [%0], [%1], 16;" :: "r"(dst), "l"(src));
}
__device__ __forceinline__ void cp_commit() { asm volatile("cp.async.commit_group;"); }
template<int N> __device__ __forceinline__ void cp_wait() {
    asm volatile("cp.async.wait_group %0;" :: "n"(N));
}

// ---------------------------------------------------------------------------
// Projection: Y[32768,64] = X[32768,512] @ W[512,64], 2-term split-tf32
// (x_hi@w + x_lo@w, w tf32-rounded per use). fp16 epilogue:
// which==0 -> g_Qh (scaled), which==1 -> g_Kh, which==2 -> g_Vt (transposed).
// ---------------------------------------------------------------------------
#define PX_PAD 36
#define PW_PAD 72
#define P_X0 0
#define P_X1 18432
#define P_W0 36864
#define P_W1 46080
#define P_TOT 55296

__global__ void __launch_bounds__(256, 2) proj_kernel(
    const float* __restrict__ Xq, const float* __restrict__ Xk, const float* __restrict__ Xv,
    const float* __restrict__ Wq, const float* __restrict__ Wk, const float* __restrict__ Wv)
{
    extern __shared__ char sm[];
    uint32_t smb = smem_to_u32(sm);

    const float* X; const float* W;
    int which = blockIdx.y;
    if (which == 0)      { X = Xq; W = Wq; }
    else if (which == 1) { X = Xk; W = Wk; }
    else                 { X = Xv; W = Wv; }

    const int tid = threadIdx.x, lane = tid & 31, warp = tid >> 5;
    const int r4 = lane >> 2, k4 = lane & 3;
    const int rowBase = blockIdx.x * 128;

    auto load_chunk = [&](int ch) {
        uint32_t xd = smb + ((ch & 1) ? P_X1 : P_X0);
        uint32_t wd = smb + ((ch & 1) ? P_W1 : P_W0);
        const float* xs = X + (size_t)rowBase * DM + ch * 32;
        #pragma unroll
        for (int i = 0; i < 4; i++) {
            int idx = tid + i * 256;
            int row = idx >> 3, c = idx & 7;
            cp16(xd + row * (PX_PAD * 4) + c * 16, xs + (size_t)row * DM + c * 4);
        }
        const float* ws = W + (size_t)(ch * 32) * 64;
        #pragma unroll
        for (int i = 0; i < 2; i++) {
            int idx = tid + i * 256;
            int row = idx >> 4, c = idx & 15;
            cp16(wd + row * (PW_PAD * 4) + c * 16, ws + row * 64 + c * 4);
        }
        cp_commit();
    };

    float acc[8][4];
    #pragma unroll
    for (int nb = 0; nb < 8; nb++)
        #pragma unroll
        for (int i = 0; i < 4; i++) acc[nb][i] = 0.0f;

    load_chunk(0);
    for (int ch = 0; ch < 16; ch++) {
        if (ch > 0) __syncthreads();
        if (ch < 15) load_chunk(ch + 1);
        if (ch < 15) cp_wait<1>(); else cp_wait<0>();
        __syncthreads();

        const float* Xs = (const float*)(sm + ((ch & 1) ? P_X1 : P_X0));
        const float* Ws = (const float*)(sm + ((ch & 1) ? P_W1 : P_W0));

        #pragma unroll
        for (int ks = 0; ks < 4; ks++) {
            const float* xp = Xs + (warp * 16 + r4) * PX_PAD + ks * 8 + k4;
            float af[4] = { xp[0], xp[8 * PX_PAD], xp[4], xp[8 * PX_PAD + 4] };
            uint32_t ahi[4], alo[4];
            #pragma unroll
            for (int i = 0; i < 4; i++) {
                uint32_t h = __float_as_uint(af[i]) & 0xffffe000u;
                ahi[i] = h;
                alo[i] = cvt_tf32(af[i] - __uint_as_float(h));
            }
            const float* wp = Ws + (ks * 8 + k4) * PW_PAD;
            #pragma unroll
            for (int nb = 0; nb < 8; nb++) {
                uint32_t bb[2] = {
                    cvt_tf32(wp[nb * 8 + r4]),
                    cvt_tf32(wp[4 * PW_PAD + nb * 8 + r4])
                };
                mma8(acc[nb], ahi, bb);
                mma8(acc[nb], alo, bb);
            }
        }
    }

    if (which == 2) {
        // V transposed fp16: g_Vt[(b*64 + d) * TT + t]
        int m = rowBase + warp * 16 + r4;
        int bq = m >> 12;
        int t = m & 4095;
        #pragma unroll
        for (int nb = 0; nb < 8; nb++) {
            int d = nb * 8 + 2 * k4;
            g_Vt[((size_t)bq * 64 + d)     * TT + t]     = __float2half_rn(acc[nb][0]);
            g_Vt[((size_t)bq * 64 + d + 1) * TT + t]     = __float2half_rn(acc[nb][1]);
            g_Vt[((size_t)bq * 64 + d)     * TT + t + 8] = __float2half_rn(acc[nb][2]);
            g_Vt[((size_t)bq * 64 + d + 1) * TT + t + 8] = __float2half_rn(acc[nb][3]);
        }
    } else {
        __half* Yh = (which == 0) ? g_Qh : g_Kh;
        const float sc = (which == 0)
            ? (0.044194173824159216f * 1.4426950408889634f) : 1.0f;
        __half* yp = Yh + (size_t)(rowBase + warp * 16) * 64;
        #pragma unroll
        for (int nb = 0; nb < 8; nb++) {
            int c = nb * 8 + 2 * k4;
            *(uint32_t*)(yp + r4 * 64 + c) =
                pack_h2(acc[nb][0] * sc, acc[nb][1] * sc);
            *(uint32_t*)(yp + (r4 + 8) * 64 + c) =
                pack_h2(acc[nb][2] * sc, acc[nb][3] * sc);
        }
    }
}

// ---------------------------------------------------------------------------
// Flash attention, fp16 m16n8k16. CTA = (128 q-rows, batch); 8 warps x m16;
// Bc=64, 64 tiles; 2 CTAs/SM; grid 256 = single wave.
// QK^T: 4 ksteps x 8 = 32 mma; PV: 32 mma. S-accum pairs pack directly into
// the PV A-fragment (no SMEM round trip, no permutation). V tile is [d][s].
// ---------------------------------------------------------------------------
#define AQ_STR 72                      // halves; row = 144 B (16B-aligned, conflict-free)
#define AK_STR 72
#define AV_STR 72
#define A_BIAS 0                       // 4096 floats = 16384
#define A_Q    16384                   // 128*144 = 18432 -> 34816
#define A_K0   34816                   // 64*144 = 9216 -> 44032
#define A_K1   44032                   // -> 53248
#define A_V0   53248                   // -> 62464
#define A_V1   62464                   // -> 71680
#define A_TOT  71680

__global__ void __launch_bounds__(256, 2) attn_kernel(
    const int* __restrict__ pad_mask, float* __restrict__ out)
{
    extern __shared__ char sm[];
    uint32_t smb = smem_to_u32(sm);
    float* biasAll = (float*)(sm + A_BIAS);

    const int tid = threadIdx.x, lane = tid & 31, warp = tid >> 5;
    const int b = blockIdx.y, qBase = blockIdx.x * 128;
    const int r4 = lane >> 2, k4 = lane & 3;

    const __half* gK  = g_Kh + (size_t)b * TT * 64;
    const __half* gVt = g_Vt + (size_t)b * 64 * TT;
    const int*    pm  = pad_mask + (size_t)b * TT;

    // stage Q tile (fp16, pre-scaled)
    {
        const __half* src = g_Qh + ((size_t)b * TT + qBase) * 64;
        #pragma unroll
        for (int i = 0; i < 4; i++) {
            int idx = tid + i * 256;
            int row = idx >> 3, c = idx & 7;
            cp16(smb + A_Q + row * (AQ_STR * 2) + c * 16, src + row * 64 + c * 8);
        }
        cp_commit();
    }

    auto load_tile = [&](int t) {
        int base = t * 64;
        uint32_t kd = smb + ((t & 1) ? A_K1 : A_K0);
        uint32_t vd = smb + ((t & 1) ? A_V1 : A_V0);
        #pragma unroll
        for (int i = 0; i < 2; i++) {
            int idx = tid + i * 256;
            int row = idx >> 3, c = idx & 7;
            cp16(kd + row * (AK_STR * 2) + c * 16, gK + (size_t)(base + row) * 64 + c * 8);
        }
        #pragma unroll
        for (int i = 0; i < 2; i++) {
            int idx = tid + i * 256;
            int d = idx >> 3, c = idx & 7;
            cp16(vd + d * (AV_STR * 2) + c * 16, gVt + (size_t)d * TT + base + c * 8);
        }
        cp_commit();
    };

    load_tile(0);

    // mask bias precompute (overlaps the async loads)
    for (int i = tid; i < TT; i += 256)
        biasAll[i] = pm[i] ? -1e30f : 0.0f;

    float o[8][4];
    float l0 = 0.0f, l1 = 0.0f;
    #pragma unroll
    for (int nb = 0; nb < 8; nb++)
        #pragma unroll
        for (int i = 0; i < 4; i++) o[nb][i] = 0.0f;

    const __half* Qs = (const __half*)(sm + A_Q);
    const int r0 = warp * 16 + r4;
    const int NT = TT / 64;

    for (int t = 0; t < NT; t++) {
        if (t > 0) __syncthreads();           // compute t-1 done -> buffer reuse OK
        if (t < NT - 1) load_tile(t + 1);
        if (t < NT - 1) cp_wait<1>(); else cp_wait<0>();
        __syncthreads();

        const __half* Ks = (const __half*)(sm + ((t & 1) ? A_K1 : A_K0));
        const __half* Vs = (const __half*)(sm + ((t & 1) ? A_V1 : A_V0));
        const float* bias = biasAll + t * 64;

        // ---- S = Q @ K^T (fp16, 4 ksteps of 16) ----
        float s[8][4];
        #pragma unroll
        for (int nb = 0; nb < 8; nb++) {
            s[nb][0] = 0.0f; s[nb][1] = 0.0f; s[nb][2] = 0.0f; s[nb][3] = 0.0f;
        }
        #pragma unroll
        for (int ks = 0; ks < 4; ks++) {
            int c0 = ks * 16 + 2 * k4;
            uint32_t a[4] = {
                *(const uint32_t*)(Qs + r0 * AQ_STR + c0),
                *(const uint32_t*)(Qs + (r0 + 8) * AQ_STR + c0),
                *(const uint32_t*)(Qs + r0 * AQ_STR + c0 + 8),
                *(const uint32_t*)(Qs + (r0 + 8) * AQ_STR + c0 + 8)
            };
            #pragma unroll
            for (int nb = 0; nb < 8; nb++) {
                const __half* kk = Ks + (nb * 8 + r4) * AK_STR + c0;
                uint32_t bb[2] = { *(const uint32_t*)(kk), *(const uint32_t*)(kk + 8) };
                mma16(s[nb], a, bb);
            }
        }

        // ---- softmax: p = exp2(s + bias); pack to f16x2 for the PV A-frags.
        uint32_t plo[8], phi[8];
        #pragma unroll
        for (int nb = 0; nb < 8; nb++) {
            int c = nb * 8 + 2 * k4;
            float2 bv = *(const float2*)(bias + c);
            float p0 = ex2f(s[nb][0] + bv.x);
            float p1 = ex2f(s[nb][1] + bv.y);
            float p2 = ex2f(s[nb][2] + bv.x);
            float p3 = ex2f(s[nb][3] + bv.y);
            l0 += p0 + p1;
            l1 += p2 + p3;
            plo[nb] = pack_h2(p0, p1);
            phi[nb] = pack_h2(p2, p3);
        }

        // ---- O += P @ V (fp16): S-acc pairs ARE the A-fragment; V tile [d][s].
        #pragma unroll
        for (int nbS = 0; nbS < 4; nbS++) {
            uint32_t a[4] = { plo[2 * nbS], phi[2 * nbS],
                              plo[2 * nbS + 1], phi[2 * nbS + 1] };
            int sc = nbS * 16 + 2 * k4;
            #pragma unroll
            for (int nb = 0; nb < 8; nb++) {
                const __half* vp = Vs + (nb * 8 + r4) * AV_STR + sc;
                uint32_t bb[2] = { *(const uint32_t*)(vp), *(const uint32_t*)(vp + 8) };
                mma16(o[nb], a, bb);
            }
        }
    }

    // reduce row-sums across the quad, normalize, store
    l0 += __shfl_xor_sync(0xffffffffu, l0, 1);
    l0 += __shfl_xor_sync(0xffffffffu, l0, 2);
    l1 += __shfl_xor_sync(0xffffffffu, l1, 1);
    l1 += __shfl_xor_sync(0xffffffffu, l1, 2);
    float i0 = 1.0f / l0, i1 = 1.0f / l1;

    float* op = out + ((size_t)b * TT + qBase + warp * 16) * 64;
    #pragma unroll
    for (int nb = 0; nb < 8; nb++) {
        int c = nb * 8 + 2 * k4;
        *(float2*)(op + r4 * 64 + c)       = make_float2(o[nb][0] * i0, o[nb][1] * i0);
        *(float2*)(op + (r4 + 8) * 64 + c) = make_float2(o[nb][2] * i1, o[nb][3] * i1);
    }
}

// ---------------------------------------------------------------------------
// kernel_launch: inputs (metadata order): k, v, q, pad_mask, Wk, Wq, Wv
// ---------------------------------------------------------------------------
extern "C" void kernel_launch(void* const* d_in, const int* in_sizes, int n_in,
                              void* d_out, int out_size)
{
    const float* k        = (const float*)d_in[0];
    const float* v        = (const float*)d_in[1];
    const float* q        = (const float*)d_in[2];
    const int*   pad_mask = (const int*)d_in[3];
    const float* Wk       = (const float*)d_in[4];
    const float* Wq       = (const float*)d_in[5];
    const float* Wv       = (const float*)d_in[6];
    float* out = (float*)d_out;

    cudaFuncSetAttribute(proj_kernel, cudaFuncAttributeMaxDynamicSharedMemorySize, P_TOT);
    dim3 pg(BB * TT / 128, 3);
    proj_kernel<<<pg, 256, P_TOT>>>(q, k, v, Wq, Wk, Wv);

    cudaFuncSetAttribute(attn_kernel, cudaFuncAttributeMaxDynamicSharedMemorySize, A_TOT);
    dim3 ag(TT / 128, BB);
    attn_kernel<<<ag, 256, A_TOT>>>(pad_mask, out);
}

// round 10
// speedup vs baseline: 1.8665x; 1.1003x over previous
#include <cuda_runtime.h>
#include <cuda_fp16.h>
#include <cstdint>

#define BB 8
#define TT 4096
#define DM 512

// projected Q, K, V scratch (fp16). Q pre-scaled by (1/sqrt(512))*log2(e).
// V stored TRANSPOSED: g_Vt[b][d][t].
__device__ __align__(256) __half g_Qh[BB * TT * 64];
__device__ __align__(256) __half g_Kh[BB * TT * 64];
__device__ __align__(256) __half g_Vt[BB * 64 * TT];

// ---------------------------------------------------------------------------
// helpers
// ---------------------------------------------------------------------------
__device__ __forceinline__ uint32_t smem_to_u32(const void* p) {
    uint32_t a;
    asm("{ .reg .u64 t; cvta.to.shared.u64 t, %1; cvt.u32.u64 %0, t; }" : "=r"(a) : "l"(p));
    return a;
}
__device__ __forceinline__ float ex2f(float x) {
    float y; asm("ex2.approx.ftz.f32 %0, %1;" : "=f"(y) : "f"(x)); return y;
}
// pack two f32 -> f16x2 (lo = first arg in low half)
__device__ __forceinline__ uint32_t pack_h2(float lo, float hi) {
    uint32_t d; asm("cvt.rn.f16x2.f32 %0, %1, %2;" : "=r"(d) : "f"(hi), "f"(lo)); return d;
}
// fp16: D += A(m16 x k16) * B(k16 x n8), f32 accumulate
__device__ __forceinline__ void mma16(float* d, const uint32_t* a, const uint32_t* b) {
    asm volatile(
        "mma.sync.aligned.m16n8k16.row.col.f32.f16.f16.f32 "
        "{%0,%1,%2,%3}, {%4,%5,%6,%7}, {%8,%9}, {%0,%1,%2,%3};"
        : "+f"(d[0]), "+f"(d[1]), "+f"(d[2]), "+f"(d[3])
        : "r"(a[0]), "r"(a[1]), "r"(a[2]), "r"(a[3]), "r"(b[0]), "r"(b[1]));
}
__device__ __forceinline__ void cp16(uint32_t dst, const void* src) {
    asm volatile("cp.async.ca.shared.global [%0], [%1], 16;" :: "r"(dst), "l"(src));
}
__device__ __forceinline__ void cp_commit() { asm volatile("cp.async.commit_group;"); }
template<int N> __device__ __forceinline__ void cp_wait() {
    asm volatile("cp.async.wait_group %0;" :: "n"(N));
}

// ---------------------------------------------------------------------------
// Projection: Y[32768,64] = X[32768,512] @ W[512,64], fp16 m16n8k16 math
// (X and W rounded to fp16 at fragment load; fp32 accumulate).
// CTA: 128 rows x 64 cols, 8 warps (each warp m16 x n64). K chunks of 32,
// double-buffered cp.async (fp32 staging).
// fp16 epilogue: which==0 -> g_Qh (scaled), 1 -> g_Kh, 2 -> g_Vt (transposed).
// ---------------------------------------------------------------------------
#define PX_PAD 36
#define PW_PAD 68   // (8*k4 + r4) mod 32 injective -> conflict-free B-frag loads
#define P_X0 0
#define P_X1 18432
#define P_W0 36864
#define P_W1 45568
#define P_TOT 54272

__global__ void __launch_bounds__(256, 2) proj_kernel(
    const float* __restrict__ Xq, const float* __restrict__ Xk, const float* __restrict__ Xv,
    const float* __restrict__ Wq, const float* __restrict__ Wk, const float* __restrict__ Wv)
{
    extern __shared__ char sm[];
    uint32_t smb = smem_to_u32(sm);

    const float* X; const float* W;
    int which = blockIdx.y;
    if (which == 0)      { X = Xq; W = Wq; }
    else if (which == 1) { X = Xk; W = Wk; }
    else                 { X = Xv; W = Wv; }

    const int tid = threadIdx.x, lane = tid & 31, warp = tid >> 5;
    const int r4 = lane >> 2, k4 = lane & 3;
    const int rowBase = blockIdx.x * 128;

    auto load_chunk = [&](int ch) {
        uint32_t xd = smb + ((ch & 1) ? P_X1 : P_X0);
        uint32_t wd = smb + ((ch & 1) ? P_W1 : P_W0);
        const float* xs = X + (size_t)rowBase * DM + ch * 32;
        #pragma unroll
        for (int i = 0; i < 4; i++) {
            int idx = tid + i * 256;
            int row = idx >> 3, c = idx & 7;
            cp16(xd + row * (PX_PAD * 4) + c * 16, xs + (size_t)row * DM + c * 4);
        }
        const float* ws = W + (size_t)(ch * 32) * 64;
        #pragma unroll
        for (int i = 0; i < 2; i++) {
            int idx = tid + i * 256;
            int row = idx >> 4, c = idx & 15;
            cp16(wd + row * (PW_PAD * 4) + c * 16, ws + row * 64 + c * 4);
        }
        cp_commit();
    };

    float acc[8][4];
    #pragma unroll
    for (int nb = 0; nb < 8; nb++)
        #pragma unroll
        for (int i = 0; i < 4; i++) acc[nb][i] = 0.0f;

    load_chunk(0);
    for (int ch = 0; ch < 16; ch++) {
        if (ch > 0) __syncthreads();
        if (ch < 15) load_chunk(ch + 1);
        if (ch < 15) cp_wait<1>(); else cp_wait<0>();
        __syncthreads();

        const float* Xs = (const float*)(sm + ((ch & 1) ? P_X1 : P_X0));
        const float* Ws = (const float*)(sm + ((ch & 1) ? P_W1 : P_W0));

        #pragma unroll
        for (int ks = 0; ks < 2; ks++) {
            int c0 = ks * 16 + 2 * k4;
            const float* xp  = Xs + (warp * 16 + r4) * PX_PAD + c0;
            const float* xp8 = xp + 8 * PX_PAD;
            uint32_t a[4] = {
                pack_h2(xp[0],  xp[1]),     // row r, k = c0, c0+1
                pack_h2(xp8[0], xp8[1]),    // row r+8
                pack_h2(xp[8],  xp[9]),     // row r, k = c0+8, c0+9
                pack_h2(xp8[8], xp8[9])     // row r+8
            };
            const float* wp = Ws + c0 * PW_PAD;
            #pragma unroll
            for (int nb = 0; nb < 8; nb++) {
                const float* wn = wp + nb * 8 + r4;
                uint32_t bb[2] = {
                    pack_h2(wn[0],          wn[PW_PAD]),       // k = c0, c0+1
                    pack_h2(wn[8 * PW_PAD], wn[9 * PW_PAD])    // k = c0+8, c0+9
                };
                mma16(acc[nb], a, bb);
            }
        }
    }

    if (which == 2) {
        // V transposed fp16: g_Vt[(b*64 + d) * TT + t]
        int m = rowBase + warp * 16 + r4;
        int bq = m >> 12;
        int t = m & 4095;
        #pragma unroll
        for (int nb = 0; nb < 8; nb++) {
            int d = nb * 8 + 2 * k4;
            g_Vt[((size_t)bq * 64 + d)     * TT + t]     = __float2half_rn(acc[nb][0]);
            g_Vt[((size_t)bq * 64 + d + 1) * TT + t]     = __float2half_rn(acc[nb][1]);
            g_Vt[((size_t)bq * 64 + d)     * TT + t + 8] = __float2half_rn(acc[nb][2]);
            g_Vt[((size_t)bq * 64 + d + 1) * TT + t + 8] = __float2half_rn(acc[nb][3]);
        }
    } else {
        __half* Yh = (which == 0) ? g_Qh : g_Kh;
        const float sc = (which == 0)
            ? (0.044194173824159216f * 1.4426950408889634f) : 1.0f;
        __half* yp = Yh + (size_t)(rowBase + warp * 16) * 64;
        #pragma unroll
        for (int nb = 0; nb < 8; nb++) {
            int c = nb * 8 + 2 * k4;
            *(uint32_t*)(yp + r4 * 64 + c) =
                pack_h2(acc[nb][0] * sc, acc[nb][1] * sc);
            *(uint32_t*)(yp + (r4 + 8) * 64 + c) =
                pack_h2(acc[nb][2] * sc, acc[nb][3] * sc);
        }
    }
}

// ---------------------------------------------------------------------------
// Flash attention, fp16 m16n8k16. CTA = (128 q-rows, batch); 8 warps x m16;
// Bc=64, 64 tiles; 2 CTAs/SM; grid 256 = single wave.
// QK^T: 4 ksteps x 8 = 32 mma; PV: 32 mma. S-accum pairs pack directly into
// the PV A-fragment (no SMEM round trip, no permutation). V tile is [d][s].
// ---------------------------------------------------------------------------
#define AQ_STR 72                      // halves; row = 144 B
#define AK_STR 72
#define AV_STR 72
#define A_BIAS 0                       // 4096 floats = 16384
#define A_Q    16384                   // 128*144 = 18432 -> 34816
#define A_K0   34816                   // 64*144 = 9216 -> 44032
#define A_K1   44032                   // -> 53248
#define A_V0   53248                   // -> 62464
#define A_V1   62464                   // -> 71680
#define A_TOT  71680

__global__ void __launch_bounds__(256, 2) attn_kernel(
    const int* __restrict__ pad_mask, float* __restrict__ out)
{
    extern __shared__ char sm[];
    uint32_t smb = smem_to_u32(sm);
    float* biasAll = (float*)(sm + A_BIAS);

    const int tid = threadIdx.x, lane = tid & 31, warp = tid >> 5;
    const int b = blockIdx.y, qBase = blockIdx.x * 128;
    const int r4 = lane >> 2, k4 = lane & 3;

    const __half* gK  = g_Kh + (size_t)b * TT * 64;
    const __half* gVt = g_Vt + (size_t)b * 64 * TT;
    const int*    pm  = pad_mask + (size_t)b * TT;

    // stage Q tile (fp16, pre-scaled)
    {
        const __half* src = g_Qh + ((size_t)b * TT + qBase) * 64;
        #pragma unroll
        for (int i = 0; i < 4; i++) {
            int idx = tid + i * 256;
            int row = idx >> 3, c = idx & 7;
            cp16(smb + A_Q + row * (AQ_STR * 2) + c * 16, src + row * 64 + c * 8);
        }
        cp_commit();
    }

    auto load_tile = [&](int t) {
        int base = t * 64;
        uint32_t kd = smb + ((t & 1) ? A_K1 : A_K0);
        uint32_t vd = smb + ((t & 1) ? A_V1 : A_V0);
        #pragma unroll
        for (int i = 0; i < 2; i++) {
            int idx = tid + i * 256;
            int row = idx >> 3, c = idx & 7;
            cp16(kd + row * (AK_STR * 2) + c * 16, gK + (size_t)(base + row) * 64 + c * 8);
        }
        #pragma unroll
        for (int i = 0; i < 2; i++) {
            int idx = tid + i * 256;
            int d = idx >> 3, c = idx & 7;
            cp16(vd + d * (AV_STR * 2) + c * 16, gVt + (size_t)d * TT + base + c * 8);
        }
        cp_commit();
    };

    load_tile(0);

    // mask bias precompute (overlaps the async loads)
    for (int i = tid; i < TT; i += 256)
        biasAll[i] = pm[i] ? -1e30f : 0.0f;

    float o[8][4];
    float l0 = 0.0f, l1 = 0.0f;
    #pragma unroll
    for (int nb = 0; nb < 8; nb++)
        #pragma unroll
        for (int i = 0; i < 4; i++) o[nb][i] = 0.0f;

    const __half* Qs = (const __half*)(sm + A_Q);
    const int r0 = warp * 16 + r4;
    const int NT = TT / 64;

    for (int t = 0; t < NT; t++) {
        if (t > 0) __syncthreads();           // compute t-1 done -> buffer reuse OK
        if (t < NT - 1) load_tile(t + 1);
        if (t < NT - 1) cp_wait<1>(); else cp_wait<0>();
        __syncthreads();

        const __half* Ks = (const __half*)(sm + ((t & 1) ? A_K1 : A_K0));
        const __half* Vs = (const __half*)(sm + ((t & 1) ? A_V1 : A_V0));
        const float* bias = biasAll + t * 64;

        // ---- S = Q @ K^T (fp16, 4 ksteps of 16) ----
        float s[8][4];
        #pragma unroll
        for (int nb = 0; nb < 8; nb++) {
            s[nb][0] = 0.0f; s[nb][1] = 0.0f; s[nb][2] = 0.0f; s[nb][3] = 0.0f;
        }
        #pragma unroll
        for (int ks = 0; ks < 4; ks++) {
            int c0 = ks * 16 + 2 * k4;
            uint32_t a[4] = {
                *(const uint32_t*)(Qs + r0 * AQ_STR + c0),
                *(const uint32_t*)(Qs + (r0 + 8) * AQ_STR + c0),
                *(const uint32_t*)(Qs + r0 * AQ_STR + c0 + 8),
                *(const uint32_t*)(Qs + (r0 + 8) * AQ_STR + c0 + 8)
            };
            #pragma unroll
            for (int nb = 0; nb < 8; nb++) {
                const __half* kk = Ks + (nb * 8 + r4) * AK_STR + c0;
                uint32_t bb[2] = { *(const uint32_t*)(kk), *(const uint32_t*)(kk + 8) };
                mma16(s[nb], a, bb);
            }
        }

        // ---- softmax: p = exp2(s + bias); pack to f16x2 for the PV A-frags.
        uint32_t plo[8], phi[8];
        #pragma unroll
        for (int nb = 0; nb < 8; nb++) {
            int c = nb * 8 + 2 * k4;
            float2 bv = *(const float2*)(bias + c);
            float p0 = ex2f(s[nb][0] + bv.x);
            float p1 = ex2f(s[nb][1] + bv.y);
            float p2 = ex2f(s[nb][2] + bv.x);
            float p3 = ex2f(s[nb][3] + bv.y);
            l0 += p0 + p1;
            l1 += p2 + p3;
            plo[nb] = pack_h2(p0, p1);
            phi[nb] = pack_h2(p2, p3);
        }

        // ---- O += P @ V (fp16): S-acc pairs ARE the A-fragment; V tile [d][s].
        #pragma unroll
        for (int nbS = 0; nbS < 4; nbS++) {
            uint32_t a[4] = { plo[2 * nbS], phi[2 * nbS],
                              plo[2 * nbS + 1], phi[2 * nbS + 1] };
            int sc = nbS * 16 + 2 * k4;
            #pragma unroll
            for (int nb = 0; nb < 8; nb++) {
                const __half* vp = Vs + (nb * 8 + r4) * AV_STR + sc;
                uint32_t bb[2] = { *(const uint32_t*)(vp), *(const uint32_t*)(vp + 8) };
                mma16(o[nb], a, bb);
            }
        }
    }

    // reduce row-sums across the quad, normalize, store
    l0 += __shfl_xor_sync(0xffffffffu, l0, 1);
    l0 += __shfl_xor_sync(0xffffffffu, l0, 2);
    l1 += __shfl_xor_sync(0xffffffffu, l1, 1);
    l1 += __shfl_xor_sync(0xffffffffu, l1, 2);
    float i0 = 1.0f / l0, i1 = 1.0f / l1;

    float* op = out + ((size_t)b * TT + qBase + warp * 16) * 64;
    #pragma unroll
    for (int nb = 0; nb < 8; nb++) {
        int c = nb * 8 + 2 * k4;
        *(float2*)(op + r4 * 64 + c)       = make_float2(o[nb][0] * i0, o[nb][1] * i0);
        *(float2*)(op + (r4 + 8) * 64 + c) = make_float2(o[nb][2] * i1, o[nb][3] * i1);
    }
}

// ---------------------------------------------------------------------------
// kernel_launch: inputs (metadata order): k, v, q, pad_mask, Wk, Wq, Wv
// ---------------------------------------------------------------------------
extern "C" void kernel_launch(void* const* d_in, const int* in_sizes, int n_in,
                              void* d_out, int out_size)
{
    const float* k        = (const float*)d_in[0];
    const float* v        = (const float*)d_in[1];
    const float* q        = (const float*)d_in[2];
    const int*   pad_mask = (const int*)d_in[3];
    const float* Wk       = (const float*)d_in[4];
    const float* Wq       = (const float*)d_in[5];
    const float* Wv       = (const float*)d_in[6];
    float* out = (float*)d_out;

    cudaFuncSetAttribute(proj_kernel, cudaFuncAttributeMaxDynamicSharedMemorySize, P_TOT);
    dim3 pg(BB * TT / 128, 3);
    proj_kernel<<<pg, 256, P_TOT>>>(q, k, v, Wq, Wk, Wv);

    cudaFuncSetAttribute(attn_kernel, cudaFuncAttributeMaxDynamicSharedMemorySize, A_TOT);
    dim3 ag(TT / 128, BB);
    attn_kernel<<<ag, 256, A_TOT>>>(pad_mask, out);
}